// round 1
// baseline (speedup 1.0000x reference)
#include <cuda_runtime.h>
#include <cstdint>
#include <cstddef>

// ---------------- problem constants ----------------
#define BN_TOT 12800      // 64 * 200 rows
#define RNN    512
#define EMB    300
#define EMBP   320        // padded embedding width (mult of 32)
#define K1     832        // EMBP + RNN  (layer1 fused K)
#define K2     1024       // RNN + RNN   (layer2 fused K)
#define NGATE  2048       // 4 * RNN
#define TSTEPS 8

// ---------------- persistent device scratch ----------------
// Double-buffered (by step parity) fused activation matrices:
//   A1[p] : [BN, K1]  cols [0,300)=tanh(emb), [300,320)=0 pad, [320,832)=h1
//   A2[p] : [BN, K2]  cols [0,512)=h1(current step), [512,1024)=h2(prev step)
__device__ float g_A1[2][(size_t)BN_TOT * K1];
__device__ float g_A2[2][(size_t)BN_TOT * K2];
__device__ float g_c1[(size_t)BN_TOT * RNN];
__device__ float g_c2[(size_t)BN_TOT * RNN];
// Packed, gate-interleaved weights: row r = 4*n + gate  (gate = i,f,g,o)
__device__ float g_W1[(size_t)NGATE * K1];
__device__ float g_W2[(size_t)NGATE * K2];
__device__ float g_b1[NGATE];
__device__ float g_b2[NGATE];

// ---------------- small helpers ----------------
__device__ __forceinline__ float to_tf32(float x) {
    uint32_t u;
    asm("cvt.rna.tf32.f32 %0, %1;" : "=r"(u) : "f"(x));
    return __uint_as_float(u);
}

__device__ __forceinline__ void cp_async16(float* dst_smem, const float* src_gmem) {
    uint32_t s = (uint32_t)__cvta_generic_to_shared(dst_smem);
    asm volatile("cp.async.cg.shared.global [%0], [%1], 16;\n" :: "r"(s), "l"(src_gmem));
}

__device__ __forceinline__ void cp_commit() {
    asm volatile("cp.async.commit_group;\n" ::: "memory");
}

__device__ __forceinline__ void mma_tf32(float* c, const uint32_t* a, uint32_t b0, uint32_t b1) {
    asm volatile(
        "mma.sync.aligned.m16n8k8.row.col.f32.tf32.tf32.f32 "
        "{%0,%1,%2,%3},{%4,%5,%6,%7},{%8,%9},{%0,%1,%2,%3};\n"
        : "+f"(c[0]), "+f"(c[1]), "+f"(c[2]), "+f"(c[3])
        : "r"(a[0]), "r"(a[1]), "r"(a[2]), "r"(a[3]), "r"(b0), "r"(b1));
}

__device__ __forceinline__ float sigmoidf_(float x) {
    return 1.f / (1.f + expf(-x));
}

// ---------------- init / pack kernels ----------------
__global__ void zero_state_kernel() {
    size_t stride = (size_t)gridDim.x * blockDim.x;
    size_t i0 = (size_t)blockIdx.x * blockDim.x + threadIdx.x;
    float* a1 = &g_A1[0][0];
    float* a2 = &g_A2[0][0];
    for (size_t i = i0; i < (size_t)2 * BN_TOT * K1; i += stride) a1[i] = 0.f;
    for (size_t i = i0; i < (size_t)2 * BN_TOT * K2; i += stride) a2[i] = 0.f;
    for (size_t i = i0; i < (size_t)BN_TOT * RNN; i += stride) { g_c1[i] = 0.f; g_c2[i] = 0.f; }
}

__global__ void pack_w1_kernel(const float* __restrict__ Wih, const float* __restrict__ Whh,
                               const float* __restrict__ bih, const float* __restrict__ bhh) {
    int idx = blockIdx.x * blockDim.x + threadIdx.x;
    if (idx >= NGATE * K1) return;
    int r = idx / K1;
    int k = idx - r * K1;
    int n = r >> 2, gate = r & 3;
    int src = gate * RNN + n;
    float v = 0.f;
    if (k < EMB)        v = Wih[(size_t)src * EMB + k];
    else if (k >= EMBP) v = Whh[(size_t)src * RNN + (k - EMBP)];
    g_W1[idx] = to_tf32(v);
    if (k == 0) g_b1[r] = bih[src] + bhh[src];
}

__global__ void pack_w2_kernel(const float* __restrict__ Wih, const float* __restrict__ Whh,
                               const float* __restrict__ bih, const float* __restrict__ bhh) {
    int idx = blockIdx.x * blockDim.x + threadIdx.x;
    if (idx >= NGATE * K2) return;
    int r = idx / K2;
    int k = idx - r * K2;
    int n = r >> 2, gate = r & 3;
    int src = gate * RNN + n;
    float v;
    if (k < RNN) v = Wih[(size_t)src * RNN + k];
    else         v = Whh[(size_t)src * RNN + (k - RNN)];
    g_W2[idx] = to_tf32(v);
    if (k == 0) g_b2[r] = bih[src] + bhh[src];
}

// embedding gather + tanh for step t, into A1[cur][:, 0:300]
__global__ void embed_step_kernel(const int* __restrict__ sent, const float* __restrict__ w2v,
                                  int t, int cur) {
    int idx = blockIdx.x * blockDim.x + threadIdx.x;
    if (idx >= BN_TOT * EMB) return;
    int bn = idx / EMB;
    int e  = idx - bn * EMB;
    int id = sent[bn * TSTEPS + t];
    float v = tanhf(w2v[(size_t)id * EMB + e]);
    g_A1[cur][(size_t)bn * K1 + e] = to_tf32(v);
}

// ---------------- fused GEMM + LSTM cell ----------------
// C[12800, 2048] = A[12800, K] @ Wpack[2048, K]^T  (gate-interleaved cols),
// then per (row m, h-col n): i,f,g,o at cols 4n..4n+3 -> LSTM cell update.
// Block tile: 128(M) x 128(N=32 h-cols) x 32(K). 256 threads, 8 warps (4x2).
// Double-buffered cp.async pipeline. Dynamic smem: 2 stages * (A+B tile, padded) = 73728 B.
template<int LAYER>
__global__ __launch_bounds__(256)
void gemm_lstm_cell(int cur, float* __restrict__ out_f32) {
    constexpr int K  = (LAYER == 1) ? K1 : K2;
    constexpr int KT = K / 32;
    const int nxt = cur ^ 1;

    const float* __restrict__ A    = (LAYER == 1) ? &g_A1[cur][0] : &g_A2[cur][0];
    const float* __restrict__ W    = (LAYER == 1) ? g_W1 : g_W2;
    const float* __restrict__ bias = (LAYER == 1) ? g_b1 : g_b2;
    float* __restrict__ Cst        = (LAYER == 1) ? g_c1 : g_c2;
    // h destinations (written tf32-rounded, they feed the next GEMMs)
    float* __restrict__ h0 = (LAYER == 1) ? (&g_A1[nxt][0] + EMBP) : (&g_A2[nxt][0] + RNN);
    const int ld0 = K;                                  // own buffer stride
    float* __restrict__ h1 = (LAYER == 1) ? &g_A2[cur][0] : nullptr;
    const int ld1 = K2;

    extern __shared__ float smem_f[];                   // 18432 floats
    const int tid  = threadIdx.x;
    const int lane = tid & 31;
    const int warp = tid >> 5;
    const int wm = warp >> 1;                           // 0..3
    const int wn = warp & 1;                            // 0..1
    const int rowBase = blockIdx.y * 128;
    const int colBase = blockIdx.x * 128;

    float acc[2][8][4];
    #pragma unroll
    for (int a = 0; a < 2; a++)
        #pragma unroll
        for (int b = 0; b < 8; b++)
            #pragma unroll
            for (int c = 0; c < 4; c++) acc[a][b][c] = 0.f;

    // ---- async tile loader: stage s <- k-tile kt ----
    // per stage: A tile 128x32 at stride 36, then B tile 128x32 at stride 36
    #define ISSUE_TILE(kt, s)                                                        \
    {                                                                                \
        float* dA = smem_f + (s) * 9216;                                             \
        float* dB = dA + 4608;                                                       \
        _Pragma("unroll")                                                            \
        for (int i = 0; i < 4; i++) {                                                \
            int t4 = tid + i * 256;                                                  \
            int r  = t4 >> 3;                                                        \
            int c4 = (t4 & 7) << 2;                                                  \
            cp_async16(dA + r * 36 + c4, A + (size_t)(rowBase + r) * K + (kt) * 32 + c4); \
            cp_async16(dB + r * 36 + c4, W + (size_t)(colBase + r) * K + (kt) * 32 + c4); \
        }                                                                            \
        cp_commit();                                                                 \
    }

    ISSUE_TILE(0, 0);
    int s = 0;
    for (int kt = 0; kt < KT; kt++) {
        if (kt + 1 < KT) {
            ISSUE_TILE(kt + 1, s ^ 1);
            asm volatile("cp.async.wait_group 1;\n" ::: "memory");
        } else {
            asm volatile("cp.async.wait_group 0;\n" ::: "memory");
        }
        __syncthreads();

        const float* pA = smem_f + s * 9216;
        const float* pB = pA + 4608;
        #pragma unroll
        for (int ks = 0; ks < 4; ks++) {
            uint32_t af[2][4];
            #pragma unroll
            for (int mt = 0; mt < 2; mt++) {
                int r0 = wm * 32 + mt * 16 + (lane >> 2);
                int c0 = ks * 8 + (lane & 3);
                af[mt][0] = __float_as_uint(pA[r0 * 36 + c0]);
                af[mt][1] = __float_as_uint(pA[(r0 + 8) * 36 + c0]);
                af[mt][2] = __float_as_uint(pA[r0 * 36 + c0 + 4]);
                af[mt][3] = __float_as_uint(pA[(r0 + 8) * 36 + c0 + 4]);
            }
            #pragma unroll
            for (int nt = 0; nt < 8; nt++) {
                int n0 = wn * 64 + nt * 8 + (lane >> 2);
                uint32_t b0 = __float_as_uint(pB[n0 * 36 + ks * 8 + (lane & 3)]);
                uint32_t b1 = __float_as_uint(pB[n0 * 36 + ks * 8 + (lane & 3) + 4]);
                mma_tf32(acc[0][nt], af[0], b0, b1);
                mma_tf32(acc[1][nt], af[1], b0, b1);
            }
        }
        __syncthreads();
        s ^= 1;
    }
    #undef ISSUE_TILE

    // ---- epilogue: accumulators -> smem gate tile -> LSTM cell ----
    float* sC = smem_f;                                 // 128 x 132 (padded)
    #pragma unroll
    for (int mt = 0; mt < 2; mt++)
        #pragma unroll
        for (int nt = 0; nt < 8; nt++) {
            int r = wm * 32 + mt * 16 + (lane >> 2);
            int c = wn * 64 + nt * 8 + ((lane & 3) << 1);
            sC[r * 132 + c]           = acc[mt][nt][0];
            sC[r * 132 + c + 1]       = acc[mt][nt][1];
            sC[(r + 8) * 132 + c]     = acc[mt][nt][2];
            sC[(r + 8) * 132 + c + 1] = acc[mt][nt][3];
        }
    __syncthreads();

    #pragma unroll
    for (int i = 0; i < 16; i++) {
        int p  = tid + i * 256;                         // 0..4095
        int ml = p >> 5;                                // 0..127 local row
        int hl = p & 31;                                // 0..31 local h col
        float4 gq = *(const float4*)&sC[ml * 132 + hl * 4];
        float4 bq = *(const float4*)&bias[colBase + hl * 4];
        float gi = gq.x + bq.x;
        float gf = gq.y + bq.y;
        float gg = gq.z + bq.z;
        float go = gq.w + bq.w;
        int gm = rowBase + ml;
        int gh = (colBase >> 2) + hl;                   // global h col 0..511
        size_t cidx = (size_t)gm * RNN + gh;
        float cold = Cst[cidx];
        float cnew = sigmoidf_(gf) * cold + sigmoidf_(gi) * tanhf(gg);
        float h    = sigmoidf_(go) * tanhf(cnew);
        Cst[cidx] = cnew;
        float ht = to_tf32(h);
        h0[(size_t)gm * ld0 + gh] = ht;
        if (h1)      h1[(size_t)gm * ld1 + gh] = ht;
        if (out_f32) out_f32[cidx] = h;                 // full fp32 final output
    }
}

// ---------------- launch ----------------
extern "C" void kernel_launch(void* const* d_in, const int* in_sizes, int n_in,
                              void* d_out, int out_size) {
    (void)in_sizes; (void)n_in; (void)out_size;
    const int*   sentence = (const int*)d_in[0];
    const float* word2vec = (const float*)d_in[1];
    const float* W_ih1 = (const float*)d_in[2];
    const float* W_hh1 = (const float*)d_in[3];
    const float* b_ih1 = (const float*)d_in[4];
    const float* b_hh1 = (const float*)d_in[5];
    const float* W_ih2 = (const float*)d_in[6];
    const float* W_hh2 = (const float*)d_in[7];
    const float* b_ih2 = (const float*)d_in[8];
    const float* b_hh2 = (const float*)d_in[9];
    float* out = (float*)d_out;

    const int SMEM_BYTES = 73728;
    cudaFuncSetAttribute(gemm_lstm_cell<1>, cudaFuncAttributeMaxDynamicSharedMemorySize, SMEM_BYTES);
    cudaFuncSetAttribute(gemm_lstm_cell<2>, cudaFuncAttributeMaxDynamicSharedMemorySize, SMEM_BYTES);

    zero_state_kernel<<<2048, 256>>>();
    pack_w1_kernel<<<(NGATE * K1 + 255) / 256, 256>>>(W_ih1, W_hh1, b_ih1, b_hh1);
    pack_w2_kernel<<<(NGATE * K2 + 255) / 256, 256>>>(W_ih2, W_hh2, b_ih2, b_hh2);

    dim3 gemm_grid(NGATE / 128, BN_TOT / 128);          // (16, 100)
    const int embed_blocks = (BN_TOT * EMB + 255) / 256;

    for (int t = 0; t < TSTEPS; t++) {
        int cur = t & 1;
        embed_step_kernel<<<embed_blocks, 256>>>(sentence, word2vec, t, cur);
        gemm_lstm_cell<1><<<gemm_grid, 256, SMEM_BYTES>>>(cur, nullptr);
        gemm_lstm_cell<2><<<gemm_grid, 256, SMEM_BYTES>>>(cur, (t == TSTEPS - 1) ? out : nullptr);
    }
}

// round 2
// speedup vs baseline: 1.0035x; 1.0035x over previous
#include <cuda_runtime.h>
#include <cstdint>
#include <cstddef>

// ---------------- problem constants ----------------
#define BN_TOT 12800      // 64 * 200 rows
#define RNN    512
#define EMB    300
#define EMBP   320        // padded embedding width (mult of 32)
#define K1     832        // EMBP + RNN  (layer1 fused K)
#define K2     1024       // RNN + RNN   (layer2 fused K)
#define NGATE  2048       // 4 * RNN
#define TSTEPS 8

// ---------------- persistent device scratch ----------------
// Double-buffered (by step parity) fused activation matrices:
//   A1[p] : [BN, K1]  cols [0,300)=tanh(emb), [300,320)=0 pad, [320,832)=h1
//   A2[p] : [BN, K2]  cols [0,512)=h1(current step), [512,1024)=h2(prev step)
__device__ float g_A1[2][(size_t)BN_TOT * K1];
__device__ float g_A2[2][(size_t)BN_TOT * K2];
__device__ float g_c1[(size_t)BN_TOT * RNN];
__device__ float g_c2[(size_t)BN_TOT * RNN];
// Packed, gate-interleaved weights: row r = 4*n + gate  (gate = i,f,g,o)
__device__ float g_W1[(size_t)NGATE * K1];
__device__ float g_W2[(size_t)NGATE * K2];
__device__ float g_b1[NGATE];
__device__ float g_b2[NGATE];

// ---------------- small helpers ----------------
__device__ __forceinline__ float to_tf32(float x) {
    uint32_t u;
    asm("cvt.rna.tf32.f32 %0, %1;" : "=r"(u) : "f"(x));
    return __uint_as_float(u);
}

__device__ __forceinline__ void cp_async16(float* dst_smem, const float* src_gmem) {
    uint32_t s = (uint32_t)__cvta_generic_to_shared(dst_smem);
    asm volatile("cp.async.cg.shared.global [%0], [%1], 16;\n" :: "r"(s), "l"(src_gmem));
}

__device__ __forceinline__ void cp_commit() {
    asm volatile("cp.async.commit_group;\n" ::: "memory");
}

__device__ __forceinline__ void mma_tf32(float* c, const uint32_t* a, uint32_t b0, uint32_t b1) {
    asm volatile(
        "mma.sync.aligned.m16n8k8.row.col.f32.tf32.tf32.f32 "
        "{%0,%1,%2,%3},{%4,%5,%6,%7},{%8,%9},{%0,%1,%2,%3};\n"
        : "+f"(c[0]), "+f"(c[1]), "+f"(c[2]), "+f"(c[3])
        : "r"(a[0]), "r"(a[1]), "r"(a[2]), "r"(a[3]), "r"(b0), "r"(b1));
}

__device__ __forceinline__ float sigmoidf_(float x) {
    return 1.f / (1.f + expf(-x));
}

// ---------------- init / pack kernels ----------------
__global__ void zero_state_kernel() {
    size_t stride = (size_t)gridDim.x * blockDim.x;
    size_t i0 = (size_t)blockIdx.x * blockDim.x + threadIdx.x;
    float* a1 = &g_A1[0][0];
    float* a2 = &g_A2[0][0];
    for (size_t i = i0; i < (size_t)2 * BN_TOT * K1; i += stride) a1[i] = 0.f;
    for (size_t i = i0; i < (size_t)2 * BN_TOT * K2; i += stride) a2[i] = 0.f;
    for (size_t i = i0; i < (size_t)BN_TOT * RNN; i += stride) { g_c1[i] = 0.f; g_c2[i] = 0.f; }
}

__global__ void pack_w1_kernel(const float* __restrict__ Wih, const float* __restrict__ Whh,
                               const float* __restrict__ bih, const float* __restrict__ bhh) {
    int idx = blockIdx.x * blockDim.x + threadIdx.x;
    if (idx >= NGATE * K1) return;
    int r = idx / K1;
    int k = idx - r * K1;
    int n = r >> 2, gate = r & 3;
    int src = gate * RNN + n;
    float v = 0.f;
    if (k < EMB)        v = Wih[(size_t)src * EMB + k];
    else if (k >= EMBP) v = Whh[(size_t)src * RNN + (k - EMBP)];
    g_W1[idx] = to_tf32(v);
    if (k == 0) g_b1[r] = bih[src] + bhh[src];
}

__global__ void pack_w2_kernel(const float* __restrict__ Wih, const float* __restrict__ Whh,
                               const float* __restrict__ bih, const float* __restrict__ bhh) {
    int idx = blockIdx.x * blockDim.x + threadIdx.x;
    if (idx >= NGATE * K2) return;
    int r = idx / K2;
    int k = idx - r * K2;
    int n = r >> 2, gate = r & 3;
    int src = gate * RNN + n;
    float v;
    if (k < RNN) v = Wih[(size_t)src * RNN + k];
    else         v = Whh[(size_t)src * RNN + (k - RNN)];
    g_W2[idx] = to_tf32(v);
    if (k == 0) g_b2[r] = bih[src] + bhh[src];
}

// embedding gather + tanh for step t, into A1[cur][:, 0:300]
__global__ void embed_step_kernel(const int* __restrict__ sent, const float* __restrict__ w2v,
                                  int t, int cur) {
    int idx = blockIdx.x * blockDim.x + threadIdx.x;
    if (idx >= BN_TOT * EMB) return;
    int bn = idx / EMB;
    int e  = idx - bn * EMB;
    int id = sent[bn * TSTEPS + t];
    float v = tanhf(w2v[(size_t)id * EMB + e]);
    g_A1[cur][(size_t)bn * K1 + e] = to_tf32(v);
}

// ---------------- fused GEMM + LSTM cell ----------------
// C[12800, 2048] = A[12800, K] @ Wpack[2048, K]^T  (gate-interleaved cols),
// then per (row m, h-col n): i,f,g,o at cols 4n..4n+3 -> LSTM cell update.
// Block tile: 128(M) x 128(N=32 h-cols) x 32(K). 256 threads, 8 warps (4x2).
// Double-buffered cp.async pipeline. Dynamic smem: 2 stages * (A+B tile, padded) = 73728 B.
template<int LAYER>
__global__ __launch_bounds__(256)
void gemm_lstm_cell(int cur, float* __restrict__ out_f32) {
    constexpr int K  = (LAYER == 1) ? K1 : K2;
    constexpr int KT = K / 32;
    const int nxt = cur ^ 1;

    const float* __restrict__ A    = (LAYER == 1) ? &g_A1[cur][0] : &g_A2[cur][0];
    const float* __restrict__ W    = (LAYER == 1) ? g_W1 : g_W2;
    const float* __restrict__ bias = (LAYER == 1) ? g_b1 : g_b2;
    float* __restrict__ Cst        = (LAYER == 1) ? g_c1 : g_c2;
    // h destinations (written tf32-rounded, they feed the next GEMMs)
    float* __restrict__ h0 = (LAYER == 1) ? (&g_A1[nxt][0] + EMBP) : (&g_A2[nxt][0] + RNN);
    const int ld0 = K;                                  // own buffer stride
    float* __restrict__ h1 = (LAYER == 1) ? &g_A2[cur][0] : nullptr;
    const int ld1 = K2;

    extern __shared__ float smem_f[];                   // 18432 floats
    const int tid  = threadIdx.x;
    const int lane = tid & 31;
    const int warp = tid >> 5;
    const int wm = warp >> 1;                           // 0..3
    const int wn = warp & 1;                            // 0..1
    const int rowBase = blockIdx.y * 128;
    const int colBase = blockIdx.x * 128;

    float acc[2][8][4];
    #pragma unroll
    for (int a = 0; a < 2; a++)
        #pragma unroll
        for (int b = 0; b < 8; b++)
            #pragma unroll
            for (int c = 0; c < 4; c++) acc[a][b][c] = 0.f;

    // ---- async tile loader: stage s <- k-tile kt ----
    // per stage: A tile 128x32 at stride 36, then B tile 128x32 at stride 36
    #define ISSUE_TILE(kt, s)                                                        \
    {                                                                                \
        float* dA = smem_f + (s) * 9216;                                             \
        float* dB = dA + 4608;                                                       \
        _Pragma("unroll")                                                            \
        for (int i = 0; i < 4; i++) {                                                \
            int t4 = tid + i * 256;                                                  \
            int r  = t4 >> 3;                                                        \
            int c4 = (t4 & 7) << 2;                                                  \
            cp_async16(dA + r * 36 + c4, A + (size_t)(rowBase + r) * K + (kt) * 32 + c4); \
            cp_async16(dB + r * 36 + c4, W + (size_t)(colBase + r) * K + (kt) * 32 + c4); \
        }                                                                            \
        cp_commit();                                                                 \
    }

    ISSUE_TILE(0, 0);
    int s = 0;
    for (int kt = 0; kt < KT; kt++) {
        if (kt + 1 < KT) {
            ISSUE_TILE(kt + 1, s ^ 1);
            asm volatile("cp.async.wait_group 1;\n" ::: "memory");
        } else {
            asm volatile("cp.async.wait_group 0;\n" ::: "memory");
        }
        __syncthreads();

        const float* pA = smem_f + s * 9216;
        const float* pB = pA + 4608;
        #pragma unroll
        for (int ks = 0; ks < 4; ks++) {
            uint32_t af[2][4];
            #pragma unroll
            for (int mt = 0; mt < 2; mt++) {
                int r0 = wm * 32 + mt * 16 + (lane >> 2);
                int c0 = ks * 8 + (lane & 3);
                af[mt][0] = __float_as_uint(pA[r0 * 36 + c0]);
                af[mt][1] = __float_as_uint(pA[(r0 + 8) * 36 + c0]);
                af[mt][2] = __float_as_uint(pA[r0 * 36 + c0 + 4]);
                af[mt][3] = __float_as_uint(pA[(r0 + 8) * 36 + c0 + 4]);
            }
            #pragma unroll
            for (int nt = 0; nt < 8; nt++) {
                int n0 = wn * 64 + nt * 8 + (lane >> 2);
                uint32_t b0 = __float_as_uint(pB[n0 * 36 + ks * 8 + (lane & 3)]);
                uint32_t b1 = __float_as_uint(pB[n0 * 36 + ks * 8 + (lane & 3) + 4]);
                mma_tf32(acc[0][nt], af[0], b0, b1);
                mma_tf32(acc[1][nt], af[1], b0, b1);
            }
        }
        __syncthreads();
        s ^= 1;
    }
    #undef ISSUE_TILE

    // ---- epilogue: accumulators -> smem gate tile -> LSTM cell ----
    float* sC = smem_f;                                 // 128 x 132 (padded)
    #pragma unroll
    for (int mt = 0; mt < 2; mt++)
        #pragma unroll
        for (int nt = 0; nt < 8; nt++) {
            int r = wm * 32 + mt * 16 + (lane >> 2);
            int c = wn * 64 + nt * 8 + ((lane & 3) << 1);
            sC[r * 132 + c]           = acc[mt][nt][0];
            sC[r * 132 + c + 1]       = acc[mt][nt][1];
            sC[(r + 8) * 132 + c]     = acc[mt][nt][2];
            sC[(r + 8) * 132 + c + 1] = acc[mt][nt][3];
        }
    __syncthreads();

    #pragma unroll
    for (int i = 0; i < 16; i++) {
        int p  = tid + i * 256;                         // 0..4095
        int ml = p >> 5;                                // 0..127 local row
        int hl = p & 31;                                // 0..31 local h col
        float4 gq = *(const float4*)&sC[ml * 132 + hl * 4];
        float4 bq = *(const float4*)&bias[colBase + hl * 4];
        float gi = gq.x + bq.x;
        float gf = gq.y + bq.y;
        float gg = gq.z + bq.z;
        float go = gq.w + bq.w;
        int gm = rowBase + ml;
        int gh = (colBase >> 2) + hl;                   // global h col 0..511
        size_t cidx = (size_t)gm * RNN + gh;
        float cold = Cst[cidx];
        float cnew = sigmoidf_(gf) * cold + sigmoidf_(gi) * tanhf(gg);
        float h    = sigmoidf_(go) * tanhf(cnew);
        Cst[cidx] = cnew;
        float ht = to_tf32(h);
        h0[(size_t)gm * ld0 + gh] = ht;
        if (h1)      h1[(size_t)gm * ld1 + gh] = ht;
        if (out_f32) out_f32[cidx] = h;                 // full fp32 final output
    }
}

// ---------------- launch ----------------
extern "C" void kernel_launch(void* const* d_in, const int* in_sizes, int n_in,
                              void* d_out, int out_size) {
    (void)in_sizes; (void)n_in; (void)out_size;
    const int*   sentence = (const int*)d_in[0];
    const float* word2vec = (const float*)d_in[1];
    const float* W_ih1 = (const float*)d_in[2];
    const float* W_hh1 = (const float*)d_in[3];
    const float* b_ih1 = (const float*)d_in[4];
    const float* b_hh1 = (const float*)d_in[5];
    const float* W_ih2 = (const float*)d_in[6];
    const float* W_hh2 = (const float*)d_in[7];
    const float* b_ih2 = (const float*)d_in[8];
    const float* b_hh2 = (const float*)d_in[9];
    float* out = (float*)d_out;

    const int SMEM_BYTES = 73728;
    cudaFuncSetAttribute(gemm_lstm_cell<1>, cudaFuncAttributeMaxDynamicSharedMemorySize, SMEM_BYTES);
    cudaFuncSetAttribute(gemm_lstm_cell<2>, cudaFuncAttributeMaxDynamicSharedMemorySize, SMEM_BYTES);

    zero_state_kernel<<<2048, 256>>>();
    pack_w1_kernel<<<(NGATE * K1 + 255) / 256, 256>>>(W_ih1, W_hh1, b_ih1, b_hh1);
    pack_w2_kernel<<<(NGATE * K2 + 255) / 256, 256>>>(W_ih2, W_hh2, b_ih2, b_hh2);

    dim3 gemm_grid(NGATE / 128, BN_TOT / 128);          // (16, 100)
    const int embed_blocks = (BN_TOT * EMB + 255) / 256;

    for (int t = 0; t < TSTEPS; t++) {
        int cur = t & 1;
        embed_step_kernel<<<embed_blocks, 256>>>(sentence, word2vec, t, cur);
        gemm_lstm_cell<1><<<gemm_grid, 256, SMEM_BYTES>>>(cur, nullptr);
        gemm_lstm_cell<2><<<gemm_grid, 256, SMEM_BYTES>>>(cur, (t == TSTEPS - 1) ? out : nullptr);
    }
}

// round 4
// speedup vs baseline: 2.1918x; 2.1842x over previous
#include <cuda_runtime.h>
#include <cuda_fp16.h>
#include <cstdint>
#include <cstddef>

#define BN_TOT 12800
#define RNN    512
#define EMB    300
#define EMBP   320
#define NGATE  2048
#define TSTEPS 8
#define K1     832     // 320 + 512
#define K2     1024    // 512 + 512

// ---------------- persistent device scratch ----------------
__device__ __half g_X[(size_t)TSTEPS * BN_TOT * EMBP];   // tanh(emb), fp16, padded
__device__ __half g_H1[2][(size_t)BN_TOT * RNN];
__device__ __half g_H2[2][(size_t)BN_TOT * RNN];
__device__ float  g_c1[(size_t)BN_TOT * RNN];
__device__ float  g_c2[(size_t)BN_TOT * RNN];
__device__ __half g_W1h[(size_t)NGATE * K1];   // row r = 4*n + gate (i,f,g,o), K-major
__device__ __half g_W2h[(size_t)NGATE * K2];
__device__ float  g_b1[NGATE];
__device__ float  g_b2[NGATE];

// ---------------- helpers ----------------
__device__ __forceinline__ uint32_t smem_u32(const void* p) {
    uint32_t a;
    asm("{ .reg .u64 t; cvta.to.shared.u64 t, %1; cvt.u32.u64 %0, t; }" : "=r"(a) : "l"(p));
    return a;
}
__device__ __forceinline__ void cp16(uint32_t dst, const void* src) {
    asm volatile("cp.async.cg.shared.global [%0], [%1], 16;\n" :: "r"(dst), "l"(src));
}
__device__ __forceinline__ void cp_commit() {
    asm volatile("cp.async.commit_group;\n" ::: "memory");
}
__device__ __forceinline__ void ldsm_x4(uint32_t* r, uint32_t addr) {
    asm volatile("ldmatrix.sync.aligned.m8n8.x4.shared.b16 {%0,%1,%2,%3}, [%4];"
                 : "=r"(r[0]), "=r"(r[1]), "=r"(r[2]), "=r"(r[3]) : "r"(addr));
}
__device__ __forceinline__ void mma16816(float* c, const uint32_t* a, uint32_t b0, uint32_t b1) {
    asm volatile(
        "mma.sync.aligned.m16n8k16.row.col.f32.f16.f16.f32 "
        "{%0,%1,%2,%3},{%4,%5,%6,%7},{%8,%9},{%0,%1,%2,%3};"
        : "+f"(c[0]), "+f"(c[1]), "+f"(c[2]), "+f"(c[3])
        : "r"(a[0]), "r"(a[1]), "r"(a[2]), "r"(a[3]), "r"(b0), "r"(b1));
}
__device__ __forceinline__ float sigm_(float x) { return __frcp_rn(1.f + __expf(-x)); }

#define STAGE_BYTES 32768                    // A 16KB + B 16KB (128 x 64 fp16 each)
#define SMEM_BYTES  98304                    // max(3 stages, epilogue 128*132*4=67584)

// ---------------- pack / embed kernels ----------------
__global__ void pack_w1(const float* __restrict__ Wih, const float* __restrict__ Whh,
                        const float* __restrict__ bih, const float* __restrict__ bhh) {
    int idx = blockIdx.x * blockDim.x + threadIdx.x;
    if (idx >= NGATE * K1) return;
    int r = idx / K1, k = idx - r * K1;
    int src = (r & 3) * RNN + (r >> 2);
    float v = 0.f;
    if (k < EMB)        v = Wih[(size_t)src * EMB + k];
    else if (k >= EMBP) v = Whh[(size_t)src * RNN + (k - EMBP)];
    g_W1h[idx] = __float2half_rn(v);
    if (k == 0) g_b1[r] = bih[src] + bhh[src];
}
__global__ void pack_w2(const float* __restrict__ Wih, const float* __restrict__ Whh,
                        const float* __restrict__ bih, const float* __restrict__ bhh) {
    int idx = blockIdx.x * blockDim.x + threadIdx.x;
    if (idx >= NGATE * K2) return;
    int r = idx / K2, k = idx - r * K2;
    int src = (r & 3) * RNN + (r >> 2);
    float v = (k < RNN) ? Wih[(size_t)src * RNN + k] : Whh[(size_t)src * RNN + (k - RNN)];
    g_W2h[idx] = __float2half_rn(v);
    if (k == 0) g_b2[r] = bih[src] + bhh[src];
}
__global__ void embed_all(const int* __restrict__ sent, const float* __restrict__ w2v) {
    int row = blockIdx.x;                    // t*BN + bn
    int t = row / BN_TOT, bn = row - t * BN_TOT;
    int e = threadIdx.x;
    int id = sent[bn * TSTEPS + t];
    float v = (e < EMB) ? tanhf(w2v[(size_t)id * EMB + e]) : 0.f;
    g_X[(size_t)row * EMBP + e] = __float2half_rn(v);
}

// ---------------- fused fp16 HMMA GEMM + LSTM cell ----------------
// C[12800,2048] = A[12800,K] @ W[2048,K]^T, gate-interleaved cols, fused cell.
// Block tile 128(M) x 128(N) x 64(K). 8 warps as 4(M) x 2(N) -> warp tile 32x64.
template<int LAYER, int FIRST>
__global__ void __launch_bounds__(256, 2) gemm_lstm(int t, int p, float* __restrict__ out) {
    constexpr int SPLIT = (LAYER == 1) ? 5 : 8;                  // chunks from part0
    constexpr int KT    = (LAYER == 1) ? (FIRST ? 5 : 13) : (FIRST ? 8 : 16);
    constexpr int S0    = (LAYER == 1) ? EMBP : RNN;
    constexpr int WLD   = (LAYER == 1) ? K1 : K2;
    const int q = p ^ 1;
    const __half* __restrict__ A0  = (LAYER == 1) ? (g_X + (size_t)t * BN_TOT * EMBP) : g_H1[q];
    const __half* __restrict__ A1  = (LAYER == 1) ? g_H1[p] : g_H2[p];
    const __half* __restrict__ Wp  = (LAYER == 1) ? g_W1h : g_W2h;
    const float*  __restrict__ bias = (LAYER == 1) ? g_b1 : g_b2;
    float* __restrict__ Cst = (LAYER == 1) ? g_c1 : g_c2;
    __half* __restrict__ Hd = (LAYER == 1) ? g_H1[q] : g_H2[q];

    extern __shared__ char smem[];
    const uint32_t sb = smem_u32(smem);
    const int tid = threadIdx.x, lane = tid & 31, warp = tid >> 5;
    const int wm = warp >> 1, wn = warp & 1;
    const int rowBase = blockIdx.y * 128;
    const int colBase = blockIdx.x * 128;
    const int lrow = lane & 15, lhalf = lane >> 4;

    float acc[2][8][4];
    #pragma unroll
    for (int a = 0; a < 2; a++)
        #pragma unroll
        for (int b = 0; b < 8; b++)
            #pragma unroll
            for (int c = 0; c < 4; c++) acc[a][b][c] = 0.f;

    auto issue = [&](int chunk, int stg) {
        uint32_t base = sb + stg * STAGE_BYTES;
        const __half* As; int stride;
        if (chunk < SPLIT) { As = A0 + (size_t)rowBase * S0 + chunk * 64; stride = S0; }
        else               { As = A1 + (size_t)rowBase * RNN + (chunk - SPLIT) * 64; stride = RNN; }
        #pragma unroll
        for (int i = 0; i < 4; i++) {
            int j = tid + i * 256; int r = j >> 3, c = j & 7;
            cp16(base + ((r * 8 + (c ^ (r & 7))) << 4), As + (size_t)r * stride + c * 8);
        }
        const __half* Bs = Wp + (size_t)colBase * WLD + chunk * 64;
        #pragma unroll
        for (int i = 0; i < 4; i++) {
            int j = tid + i * 256; int r = j >> 3, c = j & 7;
            cp16(base + 16384 + ((r * 8 + (c ^ (r & 7))) << 4), Bs + (size_t)r * WLD + c * 8);
        }
        cp_commit();
    };

    issue(0, 0);
    if (KT > 1) issue(1, 1);

    #pragma unroll 1
    for (int k = 0; k < KT; k++) {
        const int s = k % 3;
        if (k + 2 < KT) {
            issue(k + 2, (k + 2) % 3);
            asm volatile("cp.async.wait_group 2;\n" ::: "memory");
        } else if (k + 1 < KT) {
            asm volatile("cp.async.wait_group 1;\n" ::: "memory");
        } else {
            asm volatile("cp.async.wait_group 0;\n" ::: "memory");
        }
        __syncthreads();

        const uint32_t aBase = sb + s * STAGE_BYTES;
        const uint32_t bBase = aBase + 16384;
        #pragma unroll
        for (int ks = 0; ks < 4; ks++) {
            uint32_t afr[2][4];
            #pragma unroll
            for (int mt = 0; mt < 2; mt++) {
                int row = wm * 32 + mt * 16 + lrow;
                ldsm_x4(afr[mt], aBase + row * 128 + ((((ks << 1) + lhalf) ^ (row & 7)) << 4));
            }
            uint32_t bfr[4][4];
            #pragma unroll
            for (int nb = 0; nb < 4; nb++) {
                int row = wn * 64 + nb * 16 + lrow;
                ldsm_x4(bfr[nb], bBase + row * 128 + ((((ks << 1) + lhalf) ^ (row & 7)) << 4));
            }
            #pragma unroll
            for (int mt = 0; mt < 2; mt++)
                #pragma unroll
                for (int nb = 0; nb < 4; nb++) {
                    mma16816(acc[mt][2 * nb],     afr[mt], bfr[nb][0], bfr[nb][2]);
                    mma16816(acc[mt][2 * nb + 1], afr[mt], bfr[nb][1], bfr[nb][3]);
                }
        }
        __syncthreads();
    }

    // ---- epilogue: acc -> smem gate tile -> LSTM cell ----
    float* sC = (float*)smem;                            // 128 x 132
    #pragma unroll
    for (int mt = 0; mt < 2; mt++)
        #pragma unroll
        for (int nt = 0; nt < 8; nt++) {
            int r = wm * 32 + mt * 16 + (lane >> 2);
            int c = wn * 64 + nt * 8 + ((lane & 3) << 1);
            sC[r * 132 + c]           = acc[mt][nt][0];
            sC[r * 132 + c + 1]       = acc[mt][nt][1];
            sC[(r + 8) * 132 + c]     = acc[mt][nt][2];
            sC[(r + 8) * 132 + c + 1] = acc[mt][nt][3];
        }
    __syncthreads();

    #pragma unroll
    for (int i = 0; i < 4; i++) {
        int p4 = tid + i * 256;                          // 0..1023
        int ml = p4 >> 3;                                // row 0..127
        int hg = p4 & 7;                                 // group of 4 h cols
        const float* sp = &sC[ml * 132 + hg * 16];
        int gm = rowBase + ml;
        int gh = (colBase >> 2) + hg * 4;
        size_t cidx = (size_t)gm * RNN + gh;
        float4 cold = make_float4(0.f, 0.f, 0.f, 0.f);
        if (!FIRST) cold = *(const float4*)&Cst[cidx];
        float cn[4], hv[4];
        #pragma unroll
        for (int j = 0; j < 4; j++) {
            float4 gq = *(const float4*)&sp[j * 4];
            float4 bq = *(const float4*)&bias[colBase + hg * 16 + j * 4];
            float gi = gq.x + bq.x;
            float gf = gq.y + bq.y;
            float gg = gq.z + bq.z;
            float go = gq.w + bq.w;
            float co = (&cold.x)[j];
            cn[j] = sigm_(gf) * co + sigm_(gi) * tanhf(gg);
            hv[j] = sigm_(go) * tanhf(cn[j]);
        }
        *(float4*)&Cst[cidx] = make_float4(cn[0], cn[1], cn[2], cn[3]);
        __half hh[4];
        #pragma unroll
        for (int j = 0; j < 4; j++) hh[j] = __float2half_rn(hv[j]);
        *(uint2*)&Hd[(size_t)gm * RNN + gh] = *(uint2*)hh;
        if (out) *(float4*)&out[cidx] = make_float4(hv[0], hv[1], hv[2], hv[3]);
    }
}

// ---------------- launch ----------------
extern "C" void kernel_launch(void* const* d_in, const int* in_sizes, int n_in,
                              void* d_out, int out_size) {
    (void)in_sizes; (void)n_in; (void)out_size;
    const int*   sentence = (const int*)d_in[0];
    const float* word2vec = (const float*)d_in[1];
    const float* W_ih1 = (const float*)d_in[2];
    const float* W_hh1 = (const float*)d_in[3];
    const float* b_ih1 = (const float*)d_in[4];
    const float* b_hh1 = (const float*)d_in[5];
    const float* W_ih2 = (const float*)d_in[6];
    const float* W_hh2 = (const float*)d_in[7];
    const float* b_ih2 = (const float*)d_in[8];
    const float* b_hh2 = (const float*)d_in[9];
    float* out = (float*)d_out;

    cudaFuncSetAttribute(gemm_lstm<1, 1>, cudaFuncAttributeMaxDynamicSharedMemorySize, SMEM_BYTES);
    cudaFuncSetAttribute(gemm_lstm<1, 0>, cudaFuncAttributeMaxDynamicSharedMemorySize, SMEM_BYTES);
    cudaFuncSetAttribute(gemm_lstm<2, 1>, cudaFuncAttributeMaxDynamicSharedMemorySize, SMEM_BYTES);
    cudaFuncSetAttribute(gemm_lstm<2, 0>, cudaFuncAttributeMaxDynamicSharedMemorySize, SMEM_BYTES);

    pack_w1<<<(NGATE * K1 + 255) / 256, 256>>>(W_ih1, W_hh1, b_ih1, b_hh1);
    pack_w2<<<(NGATE * K2 + 255) / 256, 256>>>(W_ih2, W_hh2, b_ih2, b_hh2);
    embed_all<<<TSTEPS * BN_TOT, EMBP>>>(sentence, word2vec);

    dim3 grid(NGATE / 128, BN_TOT / 128);                // (16, 100)
    for (int t = 0; t < TSTEPS; t++) {
        int p = t & 1;
        float* o = (t == TSTEPS - 1) ? out : nullptr;
        if (t == 0) {
            gemm_lstm<1, 1><<<grid, 256, SMEM_BYTES>>>(t, p, nullptr);
            gemm_lstm<2, 1><<<grid, 256, SMEM_BYTES>>>(t, p, o);
        } else {
            gemm_lstm<1, 0><<<grid, 256, SMEM_BYTES>>>(t, p, nullptr);
            gemm_lstm<2, 0><<<grid, 256, SMEM_BYTES>>>(t, p, o);
        }
    }
}

// round 6
// speedup vs baseline: 2.3232x; 1.0599x over previous
#include <cuda_runtime.h>
#include <cuda_fp16.h>
#include <cstdint>
#include <cstddef>

#define BN_TOT 12800
#define RNN    512
#define EMB    300
#define EMBP   320
#define NGATE  2048
#define TSTEPS 8
#define K1     832     // 320 + 512
#define K2     1024    // 512 + 512

// ---------------- persistent device scratch ----------------
__device__ __half g_X[(size_t)TSTEPS * BN_TOT * EMBP];   // tanh(emb), fp16, padded
__device__ __half g_H1[2][(size_t)BN_TOT * RNN];
__device__ __half g_H2[2][(size_t)BN_TOT * RNN];
__device__ float  g_c1[(size_t)BN_TOT * RNN];
__device__ float  g_c2[(size_t)BN_TOT * RNN];
__device__ __half g_W1h[(size_t)NGATE * K1];   // row r = 4*n + gate (i,f,g,o), K-major
__device__ __half g_W2h[(size_t)NGATE * K2];
__device__ float  g_b1[NGATE];
__device__ float  g_b2[NGATE];

// ---------------- helpers ----------------
__device__ __forceinline__ uint32_t smem_u32(const void* p) {
    uint32_t a;
    asm("{ .reg .u64 t; cvta.to.shared.u64 t, %1; cvt.u32.u64 %0, t; }" : "=r"(a) : "l"(p));
    return a;
}
__device__ __forceinline__ void cp16(uint32_t dst, const void* src) {
    asm volatile("cp.async.cg.shared.global [%0], [%1], 16;\n" :: "r"(dst), "l"(src));
}
__device__ __forceinline__ void cp_commit() {
    asm volatile("cp.async.commit_group;\n" ::: "memory");
}
__device__ __forceinline__ void ldsm_x4(uint32_t* r, uint32_t addr) {
    asm volatile("ldmatrix.sync.aligned.m8n8.x4.shared.b16 {%0,%1,%2,%3}, [%4];"
                 : "=r"(r[0]), "=r"(r[1]), "=r"(r[2]), "=r"(r[3]) : "r"(addr));
}
__device__ __forceinline__ void mma16816(float* c, const uint32_t* a, uint32_t b0, uint32_t b1) {
    asm volatile(
        "mma.sync.aligned.m16n8k16.row.col.f32.f16.f16.f32 "
        "{%0,%1,%2,%3},{%4,%5,%6,%7},{%8,%9},{%0,%1,%2,%3};"
        : "+f"(c[0]), "+f"(c[1]), "+f"(c[2]), "+f"(c[3])
        : "r"(a[0]), "r"(a[1]), "r"(a[2]), "r"(a[3]), "r"(b0), "r"(b1));
}
__device__ __forceinline__ float sigm_(float x) { return __frcp_rn(1.f + __expf(-x)); }

#define STAGE_BYTES 32768
#define SMEM_BYTES  98304

// ---------------- pack / embed kernels ----------------
__global__ void pack_w1(const float* __restrict__ Wih, const float* __restrict__ Whh,
                        const float* __restrict__ bih, const float* __restrict__ bhh) {
    int idx = blockIdx.x * blockDim.x + threadIdx.x;
    if (idx >= NGATE * K1) return;
    int r = idx / K1, k = idx - r * K1;
    int src = (r & 3) * RNN + (r >> 2);
    float v = 0.f;
    if (k < EMB)        v = Wih[(size_t)src * EMB + k];
    else if (k >= EMBP) v = Whh[(size_t)src * RNN + (k - EMBP)];
    g_W1h[idx] = __float2half_rn(v);
    if (k == 0) g_b1[r] = bih[src] + bhh[src];
}
__global__ void pack_w2(const float* __restrict__ Wih, const float* __restrict__ Whh,
                        const float* __restrict__ bih, const float* __restrict__ bhh) {
    int idx = blockIdx.x * blockDim.x + threadIdx.x;
    if (idx >= NGATE * K2) return;
    int r = idx / K2, k = idx - r * K2;
    int src = (r & 3) * RNN + (r >> 2);
    float v = (k < RNN) ? Wih[(size_t)src * RNN + k] : Whh[(size_t)src * RNN + (k - RNN)];
    g_W2h[idx] = __float2half_rn(v);
    if (k == 0) g_b2[r] = bih[src] + bhh[src];
}
// one thread per half2 (2 embedding elems); row stride EMBP
__global__ void embed_all(const int* __restrict__ sent, const float* __restrict__ w2v) {
    int idx = blockIdx.x * blockDim.x + threadIdx.x;       // < T*BN*160
    if (idx >= TSTEPS * BN_TOT * (EMBP / 2)) return;
    int row = idx / (EMBP / 2);
    int e   = (idx - row * (EMBP / 2)) * 2;
    int t = row / BN_TOT, bn = row - t * BN_TOT;
    int id = __ldg(&sent[bn * TSTEPS + t]);
    float v0 = 0.f, v1 = 0.f;
    if (e < EMB) {
        const float* w = &w2v[(size_t)id * EMB + e];
        v0 = tanhf(w[0]);
        v1 = tanhf(w[1]);
    }
    ((__half2*)g_X)[idx] = __floats2half2_rn(v0, v1);
}

// ---------------- fused fp16 HMMA GEMM + LSTM cell (device core) ----------------
// C[*,2048] = A[*,K] @ W[2048,K]^T, gate-interleaved cols, fused LSTM cell.
// Block tile 128x128x64. 8 warps 4(M)x2(N), warp tile 32x64. 3-stage cp.async.
template<int SPLIT, int KT, int S0, int WLD, int FIRST>
__device__ __forceinline__ void gemm_core(
    const __half* __restrict__ A0, const __half* __restrict__ A1,
    const __half* __restrict__ Wp, const float* __restrict__ bias,
    float* __restrict__ Cst, __half* __restrict__ Hd, float* __restrict__ out,
    int rowBase, int colBase, char* smem)
{
    const uint32_t sb = smem_u32(smem);
    const int tid = threadIdx.x, lane = tid & 31, warp = tid >> 5;
    const int wm = warp >> 1, wn = warp & 1;
    const int lrow = lane & 15, lhalf = lane >> 4;

    float acc[2][8][4];
    #pragma unroll
    for (int a = 0; a < 2; a++)
        #pragma unroll
        for (int b = 0; b < 8; b++)
            #pragma unroll
            for (int c = 0; c < 4; c++) acc[a][b][c] = 0.f;

    // --- per-thread hoisted addressing ---
    const int r0 = tid >> 3;                   // 0..31
    const int c0 = tid & 7;                    // 16B column
    uint32_t dstOff[4];
    #pragma unroll
    for (int i = 0; i < 4; i++) {
        int r = r0 + 32 * i;
        dstOff[i] = (uint32_t)((r * 8 + (c0 ^ (r & 7))) << 4);
    }
    const __half* baseA0 = A0 + (size_t)(rowBase + r0) * S0  + c0 * 8;
    const __half* baseA1 = A1 + (size_t)(rowBase + r0) * RNN + c0 * 8;
    const __half* baseB  = Wp + (size_t)(colBase + r0) * WLD + c0 * 8;

    auto issue = [&](int chunk, int stg) {
        uint32_t base = sb + stg * STAGE_BYTES;
        if (chunk < SPLIT) {
            const __half* s = baseA0 + chunk * 64;
            #pragma unroll
            for (int i = 0; i < 4; i++) cp16(base + dstOff[i], s + (size_t)(32 * i) * S0);
        } else {
            const __half* s = baseA1 + (chunk - SPLIT) * 64;
            #pragma unroll
            for (int i = 0; i < 4; i++) cp16(base + dstOff[i], s + (size_t)(32 * i) * RNN);
        }
        const __half* sB = baseB + chunk * 64;
        #pragma unroll
        for (int i = 0; i < 4; i++) cp16(base + 16384 + dstOff[i], sB + (size_t)(32 * i) * WLD);
        cp_commit();
    };

    // ldsm address components (per-thread constants)
    uint32_t xks[4];
    #pragma unroll
    for (int ks = 0; ks < 4; ks++) xks[ks] = (uint32_t)((((ks << 1) + lhalf) ^ (lrow & 7)) << 4);
    uint32_t aoff[2], boff[4];
    #pragma unroll
    for (int mt = 0; mt < 2; mt++) aoff[mt] = (uint32_t)((wm * 32 + mt * 16 + lrow) * 128);
    #pragma unroll
    for (int nb = 0; nb < 4; nb++) boff[nb] = (uint32_t)((wn * 64 + nb * 16 + lrow) * 128);

    issue(0, 0);
    issue(1, 1);

    #pragma unroll 1
    for (int k = 0; k < KT; k++) {
        const int s = k % 3;
        if (k + 1 < KT) asm volatile("cp.async.wait_group 1;\n" ::: "memory");
        else            asm volatile("cp.async.wait_group 0;\n" ::: "memory");
        __syncthreads();                       // all warps done reading stage (k+2)%3 (iter k-1)
        if (k + 2 < KT) issue(k + 2, (k + 2) % 3);

        const uint32_t aBase = sb + s * STAGE_BYTES;
        const uint32_t bBase = aBase + 16384;
        #pragma unroll
        for (int ks = 0; ks < 4; ks++) {
            uint32_t afr[2][4];
            #pragma unroll
            for (int mt = 0; mt < 2; mt++) ldsm_x4(afr[mt], aBase + aoff[mt] + xks[ks]);
            uint32_t bfr[4][4];
            #pragma unroll
            for (int nb = 0; nb < 4; nb++) ldsm_x4(bfr[nb], bBase + boff[nb] + xks[ks]);
            #pragma unroll
            for (int mt = 0; mt < 2; mt++)
                #pragma unroll
                for (int nb = 0; nb < 4; nb++) {
                    mma16816(acc[mt][2 * nb],     afr[mt], bfr[nb][0], bfr[nb][2]);
                    mma16816(acc[mt][2 * nb + 1], afr[mt], bfr[nb][1], bfr[nb][3]);
                }
        }
    }
    __syncthreads();                           // before smem reuse as epilogue tile

    // ---- epilogue: acc -> smem gate tile -> LSTM cell ----
    float* sC = (float*)smem;                  // 128 x 132
    #pragma unroll
    for (int mt = 0; mt < 2; mt++)
        #pragma unroll
        for (int nt = 0; nt < 8; nt++) {
            int r = wm * 32 + mt * 16 + (lane >> 2);
            int c = wn * 64 + nt * 8 + ((lane & 3) << 1);
            sC[r * 132 + c]           = acc[mt][nt][0];
            sC[r * 132 + c + 1]       = acc[mt][nt][1];
            sC[(r + 8) * 132 + c]     = acc[mt][nt][2];
            sC[(r + 8) * 132 + c + 1] = acc[mt][nt][3];
        }
    __syncthreads();

    #pragma unroll
    for (int i = 0; i < 4; i++) {
        int p4 = tid + i * 256;                // 0..1023
        int ml = p4 >> 3;                      // row 0..127
        int hg = p4 & 7;                       // group of 4 h cols
        const float* sp = &sC[ml * 132 + hg * 16];
        int gm = rowBase + ml;
        int gh = (colBase >> 2) + hg * 4;
        size_t cidx = (size_t)gm * RNN + gh;
        float4 cold = make_float4(0.f, 0.f, 0.f, 0.f);
        if (!FIRST) cold = *(const float4*)&Cst[cidx];
        float cn[4], hv[4];
        #pragma unroll
        for (int j = 0; j < 4; j++) {
            float4 gq = *(const float4*)&sp[j * 4];
            float4 bq = *(const float4*)&bias[colBase + hg * 16 + j * 4];
            float gi = gq.x + bq.x;
            float gf = gq.y + bq.y;
            float gg = gq.z + bq.z;
            float go = gq.w + bq.w;
            float co = (&cold.x)[j];
            cn[j] = sigm_(gf) * co + sigm_(gi) * tanhf(gg);
            hv[j] = sigm_(go) * tanhf(cn[j]);
        }
        *(float4*)&Cst[cidx] = make_float4(cn[0], cn[1], cn[2], cn[3]);
        __half hh[4];
        #pragma unroll
        for (int j = 0; j < 4; j++) hh[j] = __float2half_rn(hv[j]);
        *(uint2*)&Hd[(size_t)gm * RNN + gh] = *(uint2*)hh;
        if (out) *(float4*)&out[cidx] = make_float4(hv[0], hv[1], hv[2], hv[3]);
    }
}

// ---------------- global wrappers ----------------
// Layer1 step 0 (h=c=0): only X chunks
__global__ void __launch_bounds__(256, 2) k_l1_first() {
    extern __shared__ char smem[];
    gemm_core<5, 5, EMBP, K1, 1>(g_X, g_H1[0], g_W1h, g_b1, g_c1, g_H1[1], nullptr,
                                 blockIdx.y * 128, blockIdx.x * 128, smem);
}
// Combined: layer2 step t  +  layer1 step t+1 (independent halves)
template<int FIRST2>
__global__ void __launch_bounds__(256, 2) k_step(int t) {
    extern __shared__ char smem[];
    const int p2 = t & 1, q2 = p2 ^ 1;
    if (blockIdx.y < 100) {
        gemm_core<8, (FIRST2 ? 8 : 16), RNN, K2, FIRST2>(
            g_H1[q2], g_H2[p2], g_W2h, g_b2, g_c2, g_H2[q2], nullptr,
            blockIdx.y * 128, blockIdx.x * 128, smem);
    } else {
        gemm_core<5, 13, EMBP, K1, 0>(
            g_X + (size_t)(t + 1) * BN_TOT * EMBP, g_H1[q2], g_W1h, g_b1, g_c1, g_H1[p2], nullptr,
            (blockIdx.y - 100) * 128, blockIdx.x * 128, smem);
    }
}
// Final layer2 step 7 -> writes output
__global__ void __launch_bounds__(256, 2) k_l2_last(float* __restrict__ out) {
    extern __shared__ char smem[];
    gemm_core<8, 16, RNN, K2, 0>(g_H1[0], g_H2[1], g_W2h, g_b2, g_c2, g_H2[0], out,
                                 blockIdx.y * 128, blockIdx.x * 128, smem);
}

// ---------------- launch ----------------
extern "C" void kernel_launch(void* const* d_in, const int* in_sizes, int n_in,
                              void* d_out, int out_size) {
    (void)in_sizes; (void)n_in; (void)out_size;
    const int*   sentence = (const int*)d_in[0];
    const float* word2vec = (const float*)d_in[1];
    const float* W_ih1 = (const float*)d_in[2];
    const float* W_hh1 = (const float*)d_in[3];
    const float* b_ih1 = (const float*)d_in[4];
    const float* b_hh1 = (const float*)d_in[5];
    const float* W_ih2 = (const float*)d_in[6];
    const float* W_hh2 = (const float*)d_in[7];
    const float* b_ih2 = (const float*)d_in[8];
    const float* b_hh2 = (const float*)d_in[9];
    float* out = (float*)d_out;

    cudaFuncSetAttribute(k_l1_first, cudaFuncAttributeMaxDynamicSharedMemorySize, SMEM_BYTES);
    cudaFuncSetAttribute(k_step<1>,  cudaFuncAttributeMaxDynamicSharedMemorySize, SMEM_BYTES);
    cudaFuncSetAttribute(k_step<0>,  cudaFuncAttributeMaxDynamicSharedMemorySize, SMEM_BYTES);
    cudaFuncSetAttribute(k_l2_last,  cudaFuncAttributeMaxDynamicSharedMemorySize, SMEM_BYTES);

    pack_w1<<<(NGATE * K1 + 255) / 256, 256>>>(W_ih1, W_hh1, b_ih1, b_hh1);
    pack_w2<<<(NGATE * K2 + 255) / 256, 256>>>(W_ih2, W_hh2, b_ih2, b_hh2);
    embed_all<<<(TSTEPS * BN_TOT * (EMBP / 2) + 255) / 256, 256>>>(sentence, word2vec);

    dim3 g1(16, 100), gc(16, 200);
    k_l1_first<<<g1, 256, SMEM_BYTES>>>();
    k_step<1><<<gc, 256, SMEM_BYTES>>>(0);
    for (int t = 1; t < TSTEPS - 1; t++)
        k_step<0><<<gc, 256, SMEM_BYTES>>>(t);
    k_l2_last<<<g1, 256, SMEM_BYTES>>>(out);
}